// round 14
// baseline (speedup 1.0000x reference)
#include <cuda_runtime.h>
#include <cuda_fp16.h>

// Round 14: single kernel again. R11's pair-per-block structure, but the
// scratch+transpose is fused away: levels 2p,2p+1 are ADJACENT in the
// (B,16,2) output, so a pair-block writes one float4 (16B) per point.
// One scattered STG.128 (~30 cyc/warp, R9-measured) per TWO levels
// (~15 cyc/2lv) replaces scratch store (2 cyc) + the whole 28.6us K2 +
// 64MB scratch traffic. All 8 pairs of a chunk run concurrently
// (grid.x = pair fast) so the 8x16B segments of each 128B output line
// merge in L2 (R1 evidence: no write amplification). fp16 scratch quant
// stage gone -> rel_err drops to table-only ~2.1e-4.

#define NLV 16
#define TBL 16384
#define BT  1024           // 32 warps, 1 CTA/SM (128KB: two fp16 tables)
#define NCHUNK 37          // grid (8,37) = 296 blocks = exactly 2 waves
#define SC   8192.0f
#define SCI  (1.0f / 8192.0f)

__constant__ int c_res[NLV]  = {16, 20, 25, 32, 40, 50, 64, 80,
                                101, 128, 161, 203, 256, 322, 406, 512};
__constant__ int c_nenc[NLV] = {4096, 8000, 15625, 16384, 16384, 16384, 16384, 16384,
                                16384, 16384, 16384, 16384, 16384, 16384, 16384, 16384};

__device__ __forceinline__ float2 level_compute(
    float px, float py, float pz, int res, int nenc, bool hashing,
    const __half2* __restrict__ tab)
{
    const float resf = (float)res;
    const float sx = (px + 1.0f) * resf * 0.5f - 0.5f;
    const float sy = (py + 1.0f) * resf * 0.5f - 0.5f;
    const float sz = (pz + 1.0f) * resf * 0.5f - 0.5f;
    const float flx = floorf(sx), fly = floorf(sy), flz = floorf(sz);
    const float fx = sx - flx, fy = sy - fly, fz = sz - flz;
    const int cx = (int)flx, cy = (int)fly, cz = (int)flz;

    const float wx0 = (cx >= 0)       ? 1.0f - fx : 0.0f;
    const float wx1 = (cx <  res - 1) ? fx        : 0.0f;
    const float wy0 = (cy >= 0)       ? 1.0f - fy : 0.0f;
    const float wy1 = (cy <  res - 1) ? fy        : 0.0f;
    const float wz0 = (cz >= 0)       ? 1.0f - fz : 0.0f;
    const float wz1 = (cz <  res - 1) ? fz        : 0.0f;

    const float w00 = wx0 * wy0, w01 = wx0 * wy1;
    const float w10 = wx1 * wy0, w11 = wx1 * wy1;

    unsigned id[8];
    if (hashing) {
        const unsigned hx0 = (unsigned)cx;
        const unsigned hx1 = (unsigned)(cx + 1);
        const unsigned hy0 = (unsigned)cy       * 2654435761u;
        const unsigned hy1 = (unsigned)(cy + 1) * 2654435761u;
        const unsigned hz0 = (unsigned)cz       * 805459861u;
        const unsigned hz1 = (unsigned)(cz + 1) * 805459861u;
        const unsigned g00 = hx0 ^ hy0, g01 = hx0 ^ hy1;
        const unsigned g10 = hx1 ^ hy0, g11 = hx1 ^ hy1;
        const unsigned m = (unsigned)(nenc - 1);
        id[0] = (g00 ^ hz0) & m;  id[1] = (g00 ^ hz1) & m;
        id[2] = (g01 ^ hz0) & m;  id[3] = (g01 ^ hz1) & m;
        id[4] = (g10 ^ hz0) & m;  id[5] = (g10 ^ hz1) & m;
        id[6] = (g11 ^ hz0) & m;  id[7] = (g11 ^ hz1) & m;
    } else {
        const int r2 = res * res;
        const int a0 = cx,        a1 = cx + 1;
        const int b0v = cy * res, b1v = (cy + 1) * res;
        const int c0v = cz * r2,  c1v = (cz + 1) * r2;
        const unsigned lim = (unsigned)(nenc - 1);
        id[0] = min((unsigned)(a0 + b0v + c0v), lim);
        id[1] = min((unsigned)(a0 + b0v + c1v), lim);
        id[2] = min((unsigned)(a0 + b1v + c0v), lim);
        id[3] = min((unsigned)(a0 + b1v + c1v), lim);
        id[4] = min((unsigned)(a1 + b0v + c0v), lim);
        id[5] = min((unsigned)(a1 + b0v + c1v), lim);
        id[6] = min((unsigned)(a1 + b1v + c0v), lim);
        id[7] = min((unsigned)(a1 + b1v + c1v), lim);
    }

    const float w[8] = { w00 * wz0, w00 * wz1, w01 * wz0, w01 * wz1,
                         w10 * wz0, w10 * wz1, w11 * wz0, w11 * wz1 };

    float ax = 0.0f, ay = 0.0f;
    #pragma unroll
    for (int k = 0; k < 8; k++) {
        const float2 e = __half22float2(tab[id[k]]);   // LDS.32 gather
        ax = fmaf(w[k], e.x, ax);
        ay = fmaf(w[k], e.y, ay);
    }
    return make_float2(ax, ay);
}

__global__ __launch_bounds__(BT, 1)
void hashenc_kernel(const float* __restrict__ x,
                    const float* __restrict__ emb,
                    float4* __restrict__ out,
                    int npts, int ppb)
{
    const int pair = blockIdx.x;          // 0..7
    const int lA = 2 * pair, lB = 2 * pair + 1;
    const int resA = c_res[lA],  resB = c_res[lB];
    const int neA  = c_nenc[lA], neB  = c_nenc[lB];
    const bool hA = (lA >= 3), hB = (lB >= 3);

    extern __shared__ __half2 tab[];
    __half2* tabA = tab;
    __half2* tabB = tab + TBL;
    {
        const float2* srcA = reinterpret_cast<const float2*>(emb) + lA * TBL;
        const float2* srcB = reinterpret_cast<const float2*>(emb) + lB * TBL;
        for (int i = threadIdx.x; i < neA; i += BT) {
            const float2 v = __ldg(srcA + i);
            tabA[i] = __floats2half2_rn(v.x * SC, v.y * SC);
        }
        for (int i = threadIdx.x; i < neB; i += BT) {
            const float2 v = __ldg(srcB + i);
            tabB[i] = __floats2half2_rn(v.x * SC, v.y * SC);
        }
    }
    __syncthreads();

    const int b0 = blockIdx.y * ppb;
    const int b1 = min(npts, b0 + ppb);

    for (int b = b0 + (int)threadIdx.x; b < b1; b += BT) {
        const float px = x[3 * b + 0];
        const float py = x[3 * b + 1];
        const float pz = x[3 * b + 2];
        const float2 rA = level_compute(px, py, pz, resA, neA, hA, tabA);
        const float2 rB = level_compute(px, py, pz, resB, neB, hB, tabB);
        // levels 2p,2p+1 are adjacent in (B,16,2): one float4 at
        // out[b*8 + pair]; the 8 concurrent pair-blocks fill each 128B
        // output line, merging in L2.
        out[(size_t)b * (NLV / 2) + pair] =
            make_float4(rA.x * SCI, rA.y * SCI, rB.x * SCI, rB.y * SCI);
    }
}

extern "C" void kernel_launch(void* const* d_in, const int* in_sizes, int n_in,
                              void* d_out, int out_size)
{
    const float* x   = (const float*)d_in[0];   // (B, 3) float32
    const float* emb = (const float*)d_in[1];   // (16, 16384, 2) float32
    float4* out      = (float4*)d_out;          // (B, 16, 2) float32

    const int npts = in_sizes[0] / 3;
    const int ppb  = (npts + NCHUNK - 1) / NCHUNK;
    const int smem = 2 * TBL * (int)sizeof(__half2); // 128 KB

    cudaFuncSetAttribute(hashenc_kernel,
                         cudaFuncAttributeMaxDynamicSharedMemorySize, smem);

    hashenc_kernel<<<dim3(NLV / 2, NCHUNK), BT, smem>>>(x, emb, out, npts, ppb);
}